// round 13
// baseline (speedup 1.0000x reference)
#include <cuda_runtime.h>
#include <cuda_fp16.h>
#include <cstdint>

#define NN 50000
#define EE 800000
#define INF 128
#define HIDF 128
#define OUTF 64

#define SCAN_BLK 512
#define NBLK ((NN + SCAN_BLK - 1) / SCAN_BLK)   // 98

#define SA_H 136   // A smem row stride in halves (128 + 8 pad)

// ---------------- scratch (__device__ globals; no allocation allowed) ------
__device__ uint2    g_sup0h[NN * 32];   // fp16 support0 [NN][128]
__device__ uint2    g_hh[NN * 32];      // fp16 h        [NN][128]
__device__ uint32_t g_sup1h[NN * 32];   // fp16 support1 [NN][64]
__device__ int      g_cnt0[NN];         // zeroed inside scanA each run
__device__ int      g_cnt1[NN];
__device__ int      g_ptr0[NN + 1];     // TILE-LOCAL exclusive prefixes
__device__ int      g_ptr1[NN + 1];
__device__ int      g_cur0[NN];         // tile-local cursors
__device__ int      g_cur1[NN];
__device__ int      g_bsum[2][NBLK];
__device__ int      g_boff[2][NBLK];    // global tile offsets
__device__ int      g_done0, g_done1;   // scanA arrival counters (self-reset)
__device__ int2     g_e0[EE];           // (col, val-bits) sorted by row
__device__ int2     g_e1[EE];

// ---------------- helpers --------------------------------------------------
__device__ __forceinline__ uint32_t smem_u32(const void* p) {
    uint32_t a;
    asm("{ .reg .u64 t; cvta.to.shared.u64 t, %1; cvt.u32.u64 %0, t; }"
        : "=r"(a) : "l"(p));
    return a;
}
__device__ __forceinline__ void mma_f16(float& c0, float& c1, float& c2, float& c3,
                                        uint32_t a0, uint32_t a1, uint32_t a2, uint32_t a3,
                                        uint32_t b0, uint32_t b1) {
    asm volatile(
        "mma.sync.aligned.m16n8k16.row.col.f32.f16.f16.f32 "
        "{%0,%1,%2,%3}, {%4,%5,%6,%7}, {%8,%9}, {%0,%1,%2,%3};"
        : "+f"(c0), "+f"(c1), "+f"(c2), "+f"(c3)
        : "r"(a0), "r"(a1), "r"(a2), "r"(a3), "r"(b0), "r"(b1));
}
__device__ __forceinline__ void ldsm_x2_trans(uint32_t& r0, uint32_t& r1, uint32_t addr) {
    asm volatile("ldmatrix.sync.aligned.m8n8.x2.trans.shared.b16 {%0,%1}, [%2];"
                 : "=r"(r0), "=r"(r1) : "r"(addr));
}

// ---------------- histogram (both layers, int4) ----------------------------
__global__ void hist_kernel(const int* __restrict__ row0,
                            const int* __restrict__ row1) {
    int i = blockIdx.x * blockDim.x + threadIdx.x;
    if (i < EE / 4) {
        int4 r0 = ((const int4*)row0)[i];
        atomicAdd(&g_cnt0[r0.x], 1); atomicAdd(&g_cnt0[r0.y], 1);
        atomicAdd(&g_cnt0[r0.z], 1); atomicAdd(&g_cnt0[r0.w], 1);
        int4 r1 = ((const int4*)row1)[i];
        atomicAdd(&g_cnt1[r1.x], 1); atomicAdd(&g_cnt1[r1.y], 1);
        atomicAdd(&g_cnt1[r1.z], 1); atomicAdd(&g_cnt1[r1.w], 1);
    }
}

// ---------------- scanA: tile-local scan + cnt re-zero + tile-sum scan -----
// ptr/cur hold TILE-LOCAL prefixes; consumers add g_boff[tile] lazily.
__global__ void scanA_kernel() {
    __shared__ int s[SCAN_BLK];
    __shared__ int s_last;
    int which = blockIdx.y;
    int* __restrict__ cnt = which ? g_cnt1 : g_cnt0;
    int* __restrict__ ptr = which ? g_ptr1 : g_ptr0;
    int* __restrict__ cur = which ? g_cur1 : g_cur0;
    int tid = threadIdx.x;
    int i = blockIdx.x * SCAN_BLK + tid;
    int v = 0;
    if (i < NN) {
        v = cnt[i];
        cnt[i] = 0;                  // ready for next run's hist
    }
    s[tid] = v;
    __syncthreads();
#pragma unroll
    for (int off = 1; off < SCAN_BLK; off <<= 1) {
        int t = (tid >= off) ? s[tid - off] : 0;
        __syncthreads();
        s[tid] += t;
        __syncthreads();
    }
    int excl = s[tid] - v;
    if (i <= NN) ptr[i] = excl;      // i==NN gets tile-local total prefix
    if (i < NN) cur[i] = excl;
    if (tid == SCAN_BLK - 1) g_bsum[which][blockIdx.x] = s[tid];
    __threadfence();
    if (tid == 0) {
        int* done = which ? &g_done1 : &g_done0;
        int d = atomicAdd(done, 1);
        s_last = (d == NBLK - 1);
        if (s_last) *done = 0;
    }
    __syncthreads();
    if (!s_last) return;
    __threadfence();
    __shared__ int s2[128];
    int v2 = 0;
    if (tid < 128) {
        v2 = (tid < NBLK) ? g_bsum[which][tid] : 0;
        s2[tid] = v2;
    }
    __syncthreads();
#pragma unroll
    for (int off = 1; off < 128; off <<= 1) {
        int t = (tid >= off && tid < 128) ? s2[tid - off] : 0;
        __syncthreads();
        if (tid < 128) s2[tid] += t;
        __syncthreads();
    }
    if (tid < NBLK) g_boff[which][tid] = s2[tid] - v2;
}

// ---------------- counting-sort scatter (lazy global offsets) --------------
__global__ void scatter_kernel(const int* __restrict__ row0,
                               const int* __restrict__ col0,
                               const float* __restrict__ val0,
                               const int* __restrict__ row1,
                               const int* __restrict__ col1,
                               const float* __restrict__ val1) {
    int which = blockIdx.y;
    const int* __restrict__ row = which ? row1 : row0;
    const int* __restrict__ col = which ? col1 : col0;
    const int* __restrict__ val = (const int*)(which ? val1 : val0);
    int* __restrict__ cur = which ? g_cur1 : g_cur0;
    int2* __restrict__ ed = which ? g_e1 : g_e0;
    const int* __restrict__ boff = g_boff[which];
    int i = blockIdx.x * blockDim.x + threadIdx.x;
    if (i < EE / 4) {
        int4 r = ((const int4*)row)[i];
        int4 c = ((const int4*)col)[i];
        int4 v = ((const int4*)val)[i];
        int p;
        p = atomicAdd(&cur[r.x], 1) + boff[r.x >> 9]; ed[p] = make_int2(c.x, v.x);
        p = atomicAdd(&cur[r.y], 1) + boff[r.y >> 9]; ed[p] = make_int2(c.y, v.y);
        p = atomicAdd(&cur[r.z], 1) + boff[r.z >> 9]; ed[p] = make_int2(c.z, v.z);
        p = atomicAdd(&cur[r.w], 1) + boff[r.w >> 9]; ed[p] = make_int2(c.w, v.w);
    }
}

// ---------------- GEMM 0: support0h = fp16( x @ W0 ), f16 mma --------------
__global__ void __launch_bounds__(256, 2)
gemm0_mma(const float* __restrict__ x, const float* __restrict__ W0) {
    constexpr int NC = HIDF;         // 128
    constexpr int SBn = NC + 8;      // 136
    constexpr int WN = NC / 2, NT = WN / 8;   // 64, 8
    extern __shared__ __half smh[];
    __half* As = smh;                 // [128][SA_H]
    __half* Bs = smh + 128 * SA_H;    // [128][SBn]
    int tid = threadIdx.x, wid = tid >> 5, lane = tid & 31;
    int m0 = blockIdx.x * 128;
    int wm = (wid & 3) * 32, wn = (wid >> 2) * WN;
    int gr = lane >> 2, cq = lane & 3;

    const float4* A4 = (const float4*)x;
#pragma unroll
    for (int it = 0; it < 16; it++) {
        int idx = it * 256 + tid;
        int rr = idx >> 5, c4 = idx & 31;
        float4 v = make_float4(0.f, 0.f, 0.f, 0.f);
        int grow = m0 + rr;
        if (grow < NN) v = A4[grow * 32 + c4];
        __half2 h0 = __floats2half2_rn(v.x, v.y);
        __half2 h1 = __floats2half2_rn(v.z, v.w);
        uint2 pk;
        pk.x = *(uint32_t*)&h0; pk.y = *(uint32_t*)&h1;
        *(uint2*)&As[rr * SA_H + c4 * 4] = pk;
    }
    const float4* W4 = (const float4*)W0;
#pragma unroll
    for (int it = 0; it < (128 * NC / 4) / 256; it++) {
        int idx = it * 256 + tid;
        int kk = idx / (NC / 4), c4 = idx % (NC / 4);
        float4 v = W4[idx];
        __half2 h0 = __floats2half2_rn(v.x, v.y);
        __half2 h1 = __floats2half2_rn(v.z, v.w);
        uint2 pk;
        pk.x = *(uint32_t*)&h0; pk.y = *(uint32_t*)&h1;
        *(uint2*)&Bs[kk * SBn + c4 * 4] = pk;
    }
    __syncthreads();

    float acc[2][NT][4];
#pragma unroll
    for (int im = 0; im < 2; im++)
#pragma unroll
        for (int in = 0; in < NT; in++)
#pragma unroll
            for (int q = 0; q < 4; q++) acc[im][in][q] = 0.f;

#pragma unroll
    for (int ks = 0; ks < 8; ks++) {
        int k0 = ks * 16;
        uint32_t a[2][4];
#pragma unroll
        for (int im = 0; im < 2; im++) {
            int base = wm + im * 16;
            a[im][0] = *(uint32_t*)&As[(base + gr) * SA_H + k0 + 2 * cq];
            a[im][1] = *(uint32_t*)&As[(base + gr + 8) * SA_H + k0 + 2 * cq];
            a[im][2] = *(uint32_t*)&As[(base + gr) * SA_H + k0 + 2 * cq + 8];
            a[im][3] = *(uint32_t*)&As[(base + gr + 8) * SA_H + k0 + 2 * cq + 8];
        }
#pragma unroll
        for (int in = 0; in < NT; in++) {
            int n0 = wn + in * 8;
            uint32_t baddr = smem_u32(&Bs[(k0 + (lane & 15)) * SBn + n0]);
            uint32_t b0, b1;
            ldsm_x2_trans(b0, b1, baddr);
#pragma unroll
            for (int im = 0; im < 2; im++)
                mma_f16(acc[im][in][0], acc[im][in][1], acc[im][in][2], acc[im][in][3],
                        a[im][0], a[im][1], a[im][2], a[im][3], b0, b1);
        }
    }
    __half2* C2 = (__half2*)g_sup0h;     // [NN][64] half2
#pragma unroll
    for (int im = 0; im < 2; im++) {
        int row = m0 + wm + im * 16 + gr;
#pragma unroll
        for (int in = 0; in < NT; in++) {
            int colh = (wn + in * 8 + 2 * cq) >> 1;
            if (row < NN)
                C2[row * 64 + colh] = __floats2half2_rn(acc[im][in][0], acc[im][in][1]);
            if (row + 8 < NN)
                C2[(row + 8) * 64 + colh] = __floats2half2_rn(acc[im][in][2], acc[im][in][3]);
        }
    }
}

// ---------------- GEMM 1: support1h = fp16( h @ W1 ), f16 mma --------------
__global__ void __launch_bounds__(256, 2)
gemm1_mma(const float* __restrict__ W1) {
    constexpr int NC = OUTF;          // 64
    constexpr int SBn = NC + 8;       // 72
    constexpr int WN = NC / 2, NT = WN / 8;   // 32, 4
    extern __shared__ __half smh[];
    __half* As = smh;
    __half* Bs = smh + 128 * SA_H;
    int tid = threadIdx.x, wid = tid >> 5, lane = tid & 31;
    int m0 = blockIdx.x * 128;
    int wm = (wid & 3) * 32, wn = (wid >> 2) * WN;
    int gr = lane >> 2, cq = lane & 3;

#pragma unroll
    for (int it = 0; it < 16; it++) {
        int idx = it * 256 + tid;
        int rr = idx >> 5, c = idx & 31;
        uint2 t = make_uint2(0u, 0u);
        int grow = m0 + rr;
        if (grow < NN) t = g_hh[grow * 32 + c];
        *(uint2*)&As[rr * SA_H + c * 4] = t;
    }
    const float4* W4 = (const float4*)W1;
#pragma unroll
    for (int it = 0; it < (128 * NC / 4) / 256; it++) {
        int idx = it * 256 + tid;
        int kk = idx / (NC / 4), c4 = idx % (NC / 4);
        float4 v = W4[idx];
        __half2 h0 = __floats2half2_rn(v.x, v.y);
        __half2 h1 = __floats2half2_rn(v.z, v.w);
        uint2 pk;
        pk.x = *(uint32_t*)&h0; pk.y = *(uint32_t*)&h1;
        *(uint2*)&Bs[kk * SBn + c4 * 4] = pk;
    }
    __syncthreads();

    float acc[2][NT][4];
#pragma unroll
    for (int im = 0; im < 2; im++)
#pragma unroll
        for (int in = 0; in < NT; in++)
#pragma unroll
            for (int q = 0; q < 4; q++) acc[im][in][q] = 0.f;

#pragma unroll
    for (int ks = 0; ks < 8; ks++) {
        int k0 = ks * 16;
        uint32_t a[2][4];
#pragma unroll
        for (int im = 0; im < 2; im++) {
            int base = wm + im * 16;
            a[im][0] = *(uint32_t*)&As[(base + gr) * SA_H + k0 + 2 * cq];
            a[im][1] = *(uint32_t*)&As[(base + gr + 8) * SA_H + k0 + 2 * cq];
            a[im][2] = *(uint32_t*)&As[(base + gr) * SA_H + k0 + 2 * cq + 8];
            a[im][3] = *(uint32_t*)&As[(base + gr + 8) * SA_H + k0 + 2 * cq + 8];
        }
#pragma unroll
        for (int in = 0; in < NT; in++) {
            int n0 = wn + in * 8;
            uint32_t baddr = smem_u32(&Bs[(k0 + (lane & 15)) * SBn + n0]);
            uint32_t b0, b1;
            ldsm_x2_trans(b0, b1, baddr);
#pragma unroll
            for (int im = 0; im < 2; im++)
                mma_f16(acc[im][in][0], acc[im][in][1], acc[im][in][2], acc[im][in][3],
                        a[im][0], a[im][1], a[im][2], a[im][3], b0, b1);
        }
    }
    __half2* C2 = (__half2*)g_sup1h;     // [NN][32] half2
#pragma unroll
    for (int im = 0; im < 2; im++) {
        int row = m0 + wm + im * 16 + gr;
#pragma unroll
        for (int in = 0; in < NT; in++) {
            int colh = (wn + in * 8 + 2 * cq) >> 1;
            if (row < NN)
                C2[row * 32 + colh] = __floats2half2_rn(acc[im][in][0], acc[im][in][1]);
            if (row + 8 < NN)
                C2[(row + 8) * 32 + colh] = __floats2half2_rn(acc[im][in][2], acc[im][in][3]);
        }
    }
}

// ---------------- CSR row-gather SpMM, F=128 (lazy offsets) ----------------
__global__ void spmm128_kernel(const float* __restrict__ bias) {
    int gtid = blockIdx.x * blockDim.x + threadIdx.x;
    int r = gtid >> 5;
    int lane = gtid & 31;
    if (r >= NN) return;
    int s = g_ptr0[r] + g_boff[0][r >> 9];
    int e = g_ptr0[r + 1] + g_boff[0][(r + 1) >> 9];
    float a0 = 0.f, a1 = 0.f, a2 = 0.f, a3 = 0.f;
    int i = s;
    for (; i + 1 < e; i += 2) {
        int2 ea = __ldg(&g_e0[i]);
        int2 eb = __ldg(&g_e0[i + 1]);
        uint2 ta = __ldg(&g_sup0h[ea.x * 32 + lane]);
        uint2 tb = __ldg(&g_sup0h[eb.x * 32 + lane]);
        float va = __int_as_float(ea.y), vb = __int_as_float(eb.y);
        float2 fa0 = __half22float2(*(__half2*)&ta.x);
        float2 fa1 = __half22float2(*(__half2*)&ta.y);
        float2 fb0 = __half22float2(*(__half2*)&tb.x);
        float2 fb1 = __half22float2(*(__half2*)&tb.y);
        a0 += va * fa0.x + vb * fb0.x; a1 += va * fa0.y + vb * fb0.y;
        a2 += va * fa1.x + vb * fb1.x; a3 += va * fa1.y + vb * fb1.y;
    }
    if (i < e) {
        int2 ea = __ldg(&g_e0[i]);
        float va = __int_as_float(ea.y);
        uint2 ta = __ldg(&g_sup0h[ea.x * 32 + lane]);
        float2 fa0 = __half22float2(*(__half2*)&ta.x);
        float2 fa1 = __half22float2(*(__half2*)&ta.y);
        a0 += va * fa0.x; a1 += va * fa0.y; a2 += va * fa1.x; a3 += va * fa1.y;
    }
    float4 b = ((const float4*)bias)[lane];
    a0 = fmaxf(a0 + b.x, 0.f); a1 = fmaxf(a1 + b.y, 0.f);
    a2 = fmaxf(a2 + b.z, 0.f); a3 = fmaxf(a3 + b.w, 0.f);
    uint2 o;
    *(__half2*)&o.x = __floats2half2_rn(a0, a1);
    *(__half2*)&o.y = __floats2half2_rn(a2, a3);
    g_hh[r * 32 + lane] = o;
}

// ---------------- CSR row-gather SpMM, F=64 (lazy offsets) -----------------
__global__ void spmm64_kernel(const float* __restrict__ bias,
                              float2* __restrict__ out2) {
    int gtid = blockIdx.x * blockDim.x + threadIdx.x;
    int r = gtid >> 5;
    int lane = gtid & 31;
    if (r >= NN) return;
    int s = g_ptr1[r] + g_boff[1][r >> 9];
    int e = g_ptr1[r + 1] + g_boff[1][(r + 1) >> 9];
    float a0 = 0.f, a1 = 0.f;
    int i = s;
    for (; i + 1 < e; i += 2) {
        int2 ea = __ldg(&g_e1[i]);
        int2 eb = __ldg(&g_e1[i + 1]);
        uint32_t ta = __ldg(&g_sup1h[ea.x * 32 + lane]);
        uint32_t tb = __ldg(&g_sup1h[eb.x * 32 + lane]);
        float va = __int_as_float(ea.y), vb = __int_as_float(eb.y);
        float2 fa = __half22float2(*(__half2*)&ta);
        float2 fb = __half22float2(*(__half2*)&tb);
        a0 += va * fa.x + vb * fb.x;
        a1 += va * fa.y + vb * fb.y;
    }
    if (i < e) {
        int2 ea = __ldg(&g_e1[i]);
        float va = __int_as_float(ea.y);
        uint32_t ta = __ldg(&g_sup1h[ea.x * 32 + lane]);
        float2 fa = __half22float2(*(__half2*)&ta);
        a0 += va * fa.x; a1 += va * fa.y;
    }
    float2 b = ((const float2*)bias)[lane];
    out2[r * 32 + lane] = make_float2(a0 + b.x, a1 + b.y);
}

// ---------------- launch (single stream, 7 kernels) ------------------------
extern "C" void kernel_launch(void* const* d_in, const int* in_sizes, int n_in,
                              void* d_out, int out_size) {
    const float* x    = (const float*)d_in[0];
    const int*   row0 = (const int*)d_in[1];
    const int*   col0 = (const int*)d_in[2];
    const float* val0 = (const float*)d_in[3];
    const int*   row1 = (const int*)d_in[4];
    const int*   col1 = (const int*)d_in[5];
    const float* val1 = (const float*)d_in[6];
    const float* W0   = (const float*)d_in[7];
    const float* b0   = (const float*)d_in[8];
    const float* W1   = (const float*)d_in[9];
    const float* b1   = (const float*)d_in[10];
    float* out = (float*)d_out;

    const int TB = 256;
    const int SMEM_G0 = (128 * SA_H + 128 * (HIDF + 8)) * 2;  // 69632
    const int SMEM_G1 = (128 * SA_H + 128 * (OUTF + 8)) * 2;  // 53248
    cudaFuncSetAttribute(gemm0_mma, cudaFuncAttributeMaxDynamicSharedMemorySize, SMEM_G0);
    cudaFuncSetAttribute(gemm1_mma, cudaFuncAttributeMaxDynamicSharedMemorySize, SMEM_G1);

    // 1) support0 = fp16(x @ W0)
    gemm0_mma<<<(NN + 127) / 128, 256, SMEM_G0>>>(x, W0);

    // 2) histogram both layers
    hist_kernel<<<(EE / 4 + TB - 1) / TB, TB>>>(row0, row1);

    // 3) scanA: tile-local scans, cnt re-zero, tile-offset scan
    {
        dim3 g(NBLK, 2);
        scanA_kernel<<<g, SCAN_BLK>>>();
    }

    // 4) counting-sort scatter (lazy global offsets)
    {
        dim3 gs((EE / 4 + TB - 1) / TB, 2);
        scatter_kernel<<<gs, TB>>>(row0, col0, val0, row1, col1, val1);
    }

    // 5) h = fp16(relu(spmm(adj0, support0) + b0))
    spmm128_kernel<<<(NN * 32 + TB - 1) / TB, TB>>>(b0);

    // 6) support1 = fp16(h @ W1)
    gemm1_mma<<<(NN + 127) / 128, 256, SMEM_G1>>>(W1);

    // 7) out = spmm(adj1, support1) + b1
    spmm64_kernel<<<(NN * 32 + TB - 1) / TB, TB>>>(b1, (float2*)out);
}

// round 14
// speedup vs baseline: 1.3550x; 1.3550x over previous
#include <cuda_runtime.h>
#include <cuda_fp16.h>
#include <cstdint>

#define NN 50000
#define EE 800000
#define INF 128
#define HIDF 128
#define OUTF 64

#define SCAN_BLK 512
#define NBLK ((NN + SCAN_BLK - 1) / SCAN_BLK)   // 98

#define SA_H 136   // A smem row stride in halves (128 + 8 pad)

// ---------------- scratch (__device__ globals; no allocation allowed) ------
__device__ uint2    g_sup0h[NN * 32];   // fp16 support0 [NN][128]
__device__ uint2    g_hh[NN * 32];      // fp16 h        [NN][128]
__device__ uint32_t g_sup1h[NN * 32];   // fp16 support1 [NN][64]
__device__ int      g_cnt0[NN];         // re-zeroed by scanB each run
__device__ int      g_cnt1[NN];
__device__ int      g_ptr0[NN + 1];
__device__ int      g_ptr1[NN + 1];
__device__ int      g_cur0[NN];
__device__ int      g_cur1[NN];
__device__ int      g_bsum[2][NBLK];
__device__ int      g_boff[2][NBLK];
__device__ int      g_done0, g_done1;   // scanA arrival counters (self-reset)
__device__ int2     g_e0[EE];           // (col, val-bits) sorted by row
__device__ int2     g_e1[EE];

// ---------------- helpers --------------------------------------------------
__device__ __forceinline__ uint32_t smem_u32(const void* p) {
    uint32_t a;
    asm("{ .reg .u64 t; cvta.to.shared.u64 t, %1; cvt.u32.u64 %0, t; }"
        : "=r"(a) : "l"(p));
    return a;
}
__device__ __forceinline__ void mma_f16(float& c0, float& c1, float& c2, float& c3,
                                        uint32_t a0, uint32_t a1, uint32_t a2, uint32_t a3,
                                        uint32_t b0, uint32_t b1) {
    asm volatile(
        "mma.sync.aligned.m16n8k16.row.col.f32.f16.f16.f32 "
        "{%0,%1,%2,%3}, {%4,%5,%6,%7}, {%8,%9}, {%0,%1,%2,%3};"
        : "+f"(c0), "+f"(c1), "+f"(c2), "+f"(c3)
        : "r"(a0), "r"(a1), "r"(a2), "r"(a3), "r"(b0), "r"(b1));
}
__device__ __forceinline__ void ldsm_x2_trans(uint32_t& r0, uint32_t& r1, uint32_t addr) {
    asm volatile("ldmatrix.sync.aligned.m8n8.x2.trans.shared.b16 {%0,%1}, [%2];"
                 : "=r"(r0), "=r"(r1) : "r"(addr));
}

// ---------------- histogram (both layers, int4) ----------------------------
__global__ void hist_kernel(const int* __restrict__ row0,
                            const int* __restrict__ row1) {
    int i = blockIdx.x * blockDim.x + threadIdx.x;
    if (i < EE / 4) {
        int4 r0 = ((const int4*)row0)[i];
        atomicAdd(&g_cnt0[r0.x], 1); atomicAdd(&g_cnt0[r0.y], 1);
        atomicAdd(&g_cnt0[r0.z], 1); atomicAdd(&g_cnt0[r0.w], 1);
        int4 r1 = ((const int4*)row1)[i];
        atomicAdd(&g_cnt1[r1.x], 1); atomicAdd(&g_cnt1[r1.y], 1);
        atomicAdd(&g_cnt1[r1.z], 1); atomicAdd(&g_cnt1[r1.w], 1);
    }
}

// ---------------- scanA: block-local scan + last-block scans block sums ----
__global__ void scanA_kernel() {
    __shared__ int s[SCAN_BLK];
    __shared__ int s_last;
    int which = blockIdx.y;
    const int* __restrict__ cnt = which ? g_cnt1 : g_cnt0;
    int* __restrict__ ptr = which ? g_ptr1 : g_ptr0;
    int tid = threadIdx.x;
    int i = blockIdx.x * SCAN_BLK + tid;
    int v = (i < NN) ? cnt[i] : 0;
    s[tid] = v;
    __syncthreads();
#pragma unroll
    for (int off = 1; off < SCAN_BLK; off <<= 1) {
        int t = (tid >= off) ? s[tid - off] : 0;
        __syncthreads();
        s[tid] += t;
        __syncthreads();
    }
    if (i < NN) ptr[i] = s[tid] - v;
    if (tid == SCAN_BLK - 1) g_bsum[which][blockIdx.x] = s[tid];
    __threadfence();
    if (tid == 0) {
        int* done = which ? &g_done1 : &g_done0;
        int d = atomicAdd(done, 1);
        s_last = (d == NBLK - 1);
        if (s_last) *done = 0;
    }
    __syncthreads();
    if (!s_last) return;
    __threadfence();
    __shared__ int s2[128];
    int v2 = 0;
    if (tid < 128) {
        v2 = (tid < NBLK) ? g_bsum[which][tid] : 0;
        s2[tid] = v2;
    }
    __syncthreads();
#pragma unroll
    for (int off = 1; off < 128; off <<= 1) {
        int t = (tid >= off && tid < 128) ? s2[tid - off] : 0;
        __syncthreads();
        if (tid < 128) s2[tid] += t;
        __syncthreads();
    }
    if (tid < NBLK) g_boff[which][tid] = s2[tid] - v2;
    if (tid == NBLK - 1) ptr[NN] = s2[tid];
}

// ---------------- scanB: add offsets, init cursors, re-zero counts ---------
__global__ void scanB_kernel() {
    int which = blockIdx.y;
    int* __restrict__ ptr = which ? g_ptr1 : g_ptr0;
    int* __restrict__ cur = which ? g_cur1 : g_cur0;
    int* __restrict__ cnt = which ? g_cnt1 : g_cnt0;
    int i = blockIdx.x * SCAN_BLK + threadIdx.x;
    if (i < NN) {
        int v = ptr[i] + g_boff[which][blockIdx.x];
        ptr[i] = v;
        cur[i] = v;
        cnt[i] = 0;
    }
}

// ---------------- counting-sort scatter (8 edges/thread, int2 payload) -----
__global__ void scatter_kernel(const int* __restrict__ row0,
                               const int* __restrict__ col0,
                               const float* __restrict__ val0,
                               const int* __restrict__ row1,
                               const int* __restrict__ col1,
                               const float* __restrict__ val1) {
    int which = blockIdx.y;
    const int* __restrict__ row = which ? row1 : row0;
    const int* __restrict__ col = which ? col1 : col0;
    const int* __restrict__ val = (const int*)(which ? val1 : val0);
    int* __restrict__ cur = which ? g_cur1 : g_cur0;
    int2* __restrict__ ed = which ? g_e1 : g_e0;
    int i = (blockIdx.x * blockDim.x + threadIdx.x) * 2;   // 2 int4 groups
#pragma unroll
    for (int g = 0; g < 2; g++) {
        int j = i + g;
        if (j < EE / 4) {
            int4 r = ((const int4*)row)[j];
            int4 c = ((const int4*)col)[j];
            int4 v = ((const int4*)val)[j];
            int p;
            p = atomicAdd(&cur[r.x], 1); ed[p] = make_int2(c.x, v.x);
            p = atomicAdd(&cur[r.y], 1); ed[p] = make_int2(c.y, v.y);
            p = atomicAdd(&cur[r.z], 1); ed[p] = make_int2(c.z, v.z);
            p = atomicAdd(&cur[r.w], 1); ed[p] = make_int2(c.w, v.w);
        }
    }
}

// ---------------- GEMM 0: support0h = fp16( x @ W0 ), f16 mma --------------
__global__ void __launch_bounds__(256, 2)
gemm0_mma(const float* __restrict__ x, const float* __restrict__ W0) {
    constexpr int NC = HIDF;         // 128
    constexpr int SBn = NC + 8;      // 136
    constexpr int WN = NC / 2, NT = WN / 8;   // 64, 8
    extern __shared__ __half smh[];
    __half* As = smh;                 // [128][SA_H]
    __half* Bs = smh + 128 * SA_H;    // [128][SBn]
    int tid = threadIdx.x, wid = tid >> 5, lane = tid & 31;
    int m0 = blockIdx.x * 128;
    int wm = (wid & 3) * 32, wn = (wid >> 2) * WN;
    int gr = lane >> 2, cq = lane & 3;

    const float4* A4 = (const float4*)x;
#pragma unroll
    for (int it = 0; it < 16; it++) {
        int idx = it * 256 + tid;
        int rr = idx >> 5, c4 = idx & 31;
        float4 v = make_float4(0.f, 0.f, 0.f, 0.f);
        int grow = m0 + rr;
        if (grow < NN) v = A4[grow * 32 + c4];
        __half2 h0 = __floats2half2_rn(v.x, v.y);
        __half2 h1 = __floats2half2_rn(v.z, v.w);
        uint2 pk;
        pk.x = *(uint32_t*)&h0; pk.y = *(uint32_t*)&h1;
        *(uint2*)&As[rr * SA_H + c4 * 4] = pk;
    }
    const float4* W4 = (const float4*)W0;
#pragma unroll
    for (int it = 0; it < (128 * NC / 4) / 256; it++) {
        int idx = it * 256 + tid;
        int kk = idx / (NC / 4), c4 = idx % (NC / 4);
        float4 v = W4[idx];
        __half2 h0 = __floats2half2_rn(v.x, v.y);
        __half2 h1 = __floats2half2_rn(v.z, v.w);
        uint2 pk;
        pk.x = *(uint32_t*)&h0; pk.y = *(uint32_t*)&h1;
        *(uint2*)&Bs[kk * SBn + c4 * 4] = pk;
    }
    __syncthreads();

    float acc[2][NT][4];
#pragma unroll
    for (int im = 0; im < 2; im++)
#pragma unroll
        for (int in = 0; in < NT; in++)
#pragma unroll
            for (int q = 0; q < 4; q++) acc[im][in][q] = 0.f;

#pragma unroll
    for (int ks = 0; ks < 8; ks++) {
        int k0 = ks * 16;
        uint32_t a[2][4];
#pragma unroll
        for (int im = 0; im < 2; im++) {
            int base = wm + im * 16;
            a[im][0] = *(uint32_t*)&As[(base + gr) * SA_H + k0 + 2 * cq];
            a[im][1] = *(uint32_t*)&As[(base + gr + 8) * SA_H + k0 + 2 * cq];
            a[im][2] = *(uint32_t*)&As[(base + gr) * SA_H + k0 + 2 * cq + 8];
            a[im][3] = *(uint32_t*)&As[(base + gr + 8) * SA_H + k0 + 2 * cq + 8];
        }
#pragma unroll
        for (int in = 0; in < NT; in++) {
            int n0 = wn + in * 8;
            uint32_t baddr = smem_u32(&Bs[(k0 + (lane & 15)) * SBn + n0]);
            uint32_t b0, b1;
            ldsm_x2_trans(b0, b1, baddr);
#pragma unroll
            for (int im = 0; im < 2; im++)
                mma_f16(acc[im][in][0], acc[im][in][1], acc[im][in][2], acc[im][in][3],
                        a[im][0], a[im][1], a[im][2], a[im][3], b0, b1);
        }
    }
    __half2* C2 = (__half2*)g_sup0h;     // [NN][64] half2
#pragma unroll
    for (int im = 0; im < 2; im++) {
        int row = m0 + wm + im * 16 + gr;
#pragma unroll
        for (int in = 0; in < NT; in++) {
            int colh = (wn + in * 8 + 2 * cq) >> 1;
            if (row < NN)
                C2[row * 64 + colh] = __floats2half2_rn(acc[im][in][0], acc[im][in][1]);
            if (row + 8 < NN)
                C2[(row + 8) * 64 + colh] = __floats2half2_rn(acc[im][in][2], acc[im][in][3]);
        }
    }
}

// ---------------- GEMM 1: support1h = fp16( h @ W1 ), f16 mma --------------
__global__ void __launch_bounds__(256, 2)
gemm1_mma(const float* __restrict__ W1) {
    constexpr int NC = OUTF;          // 64
    constexpr int SBn = NC + 8;       // 72
    constexpr int WN = NC / 2, NT = WN / 8;   // 32, 4
    extern __shared__ __half smh[];
    __half* As = smh;
    __half* Bs = smh + 128 * SA_H;
    int tid = threadIdx.x, wid = tid >> 5, lane = tid & 31;
    int m0 = blockIdx.x * 128;
    int wm = (wid & 3) * 32, wn = (wid >> 2) * WN;
    int gr = lane >> 2, cq = lane & 3;

#pragma unroll
    for (int it = 0; it < 16; it++) {
        int idx = it * 256 + tid;
        int rr = idx >> 5, c = idx & 31;
        uint2 t = make_uint2(0u, 0u);
        int grow = m0 + rr;
        if (grow < NN) t = g_hh[grow * 32 + c];
        *(uint2*)&As[rr * SA_H + c * 4] = t;
    }
    const float4* W4 = (const float4*)W1;
#pragma unroll
    for (int it = 0; it < (128 * NC / 4) / 256; it++) {
        int idx = it * 256 + tid;
        int kk = idx / (NC / 4), c4 = idx % (NC / 4);
        float4 v = W4[idx];
        __half2 h0 = __floats2half2_rn(v.x, v.y);
        __half2 h1 = __floats2half2_rn(v.z, v.w);
        uint2 pk;
        pk.x = *(uint32_t*)&h0; pk.y = *(uint32_t*)&h1;
        *(uint2*)&Bs[kk * SBn + c4 * 4] = pk;
    }
    __syncthreads();

    float acc[2][NT][4];
#pragma unroll
    for (int im = 0; im < 2; im++)
#pragma unroll
        for (int in = 0; in < NT; in++)
#pragma unroll
            for (int q = 0; q < 4; q++) acc[im][in][q] = 0.f;

#pragma unroll
    for (int ks = 0; ks < 8; ks++) {
        int k0 = ks * 16;
        uint32_t a[2][4];
#pragma unroll
        for (int im = 0; im < 2; im++) {
            int base = wm + im * 16;
            a[im][0] = *(uint32_t*)&As[(base + gr) * SA_H + k0 + 2 * cq];
            a[im][1] = *(uint32_t*)&As[(base + gr + 8) * SA_H + k0 + 2 * cq];
            a[im][2] = *(uint32_t*)&As[(base + gr) * SA_H + k0 + 2 * cq + 8];
            a[im][3] = *(uint32_t*)&As[(base + gr + 8) * SA_H + k0 + 2 * cq + 8];
        }
#pragma unroll
        for (int in = 0; in < NT; in++) {
            int n0 = wn + in * 8;
            uint32_t baddr = smem_u32(&Bs[(k0 + (lane & 15)) * SBn + n0]);
            uint32_t b0, b1;
            ldsm_x2_trans(b0, b1, baddr);
#pragma unroll
            for (int im = 0; im < 2; im++)
                mma_f16(acc[im][in][0], acc[im][in][1], acc[im][in][2], acc[im][in][3],
                        a[im][0], a[im][1], a[im][2], a[im][3], b0, b1);
        }
    }
    __half2* C2 = (__half2*)g_sup1h;     // [NN][32] half2
#pragma unroll
    for (int im = 0; im < 2; im++) {
        int row = m0 + wm + im * 16 + gr;
#pragma unroll
        for (int in = 0; in < NT; in++) {
            int colh = (wn + in * 8 + 2 * cq) >> 1;
            if (row < NN)
                C2[row * 32 + colh] = __floats2half2_rn(acc[im][in][0], acc[im][in][1]);
            if (row + 8 < NN)
                C2[(row + 8) * 32 + colh] = __floats2half2_rn(acc[im][in][2], acc[im][in][3]);
        }
    }
}

// ---------------- CSR row-gather SpMM, F=128 fp16 in, fp16 out -------------
__global__ void spmm128_kernel(const float* __restrict__ bias) {
    int gtid = blockIdx.x * blockDim.x + threadIdx.x;
    int r = gtid >> 5;
    int lane = gtid & 31;
    if (r >= NN) return;
    int s = g_ptr0[r], e = g_ptr0[r + 1];
    float a0 = 0.f, a1 = 0.f, a2 = 0.f, a3 = 0.f;
    int i = s;
    for (; i + 1 < e; i += 2) {
        int2 ea = __ldg(&g_e0[i]);
        int2 eb = __ldg(&g_e0[i + 1]);
        uint2 ta = __ldg(&g_sup0h[ea.x * 32 + lane]);
        uint2 tb = __ldg(&g_sup0h[eb.x * 32 + lane]);
        float va = __int_as_float(ea.y), vb = __int_as_float(eb.y);
        float2 fa0 = __half22float2(*(__half2*)&ta.x);
        float2 fa1 = __half22float2(*(__half2*)&ta.y);
        float2 fb0 = __half22float2(*(__half2*)&tb.x);
        float2 fb1 = __half22float2(*(__half2*)&tb.y);
        a0 += va * fa0.x + vb * fb0.x; a1 += va * fa0.y + vb * fb0.y;
        a2 += va * fa1.x + vb * fb1.x; a3 += va * fa1.y + vb * fb1.y;
    }
    if (i < e) {
        int2 ea = __ldg(&g_e0[i]);
        float va = __int_as_float(ea.y);
        uint2 ta = __ldg(&g_sup0h[ea.x * 32 + lane]);
        float2 fa0 = __half22float2(*(__half2*)&ta.x);
        float2 fa1 = __half22float2(*(__half2*)&ta.y);
        a0 += va * fa0.x; a1 += va * fa0.y; a2 += va * fa1.x; a3 += va * fa1.y;
    }
    float4 b = ((const float4*)bias)[lane];
    a0 = fmaxf(a0 + b.x, 0.f); a1 = fmaxf(a1 + b.y, 0.f);
    a2 = fmaxf(a2 + b.z, 0.f); a3 = fmaxf(a3 + b.w, 0.f);
    uint2 o;
    *(__half2*)&o.x = __floats2half2_rn(a0, a1);
    *(__half2*)&o.y = __floats2half2_rn(a2, a3);
    g_hh[r * 32 + lane] = o;
}

// ---------------- CSR row-gather SpMM, F=64 fp16 in, fp32 out --------------
__global__ void spmm64_kernel(const float* __restrict__ bias,
                              float2* __restrict__ out2) {
    int gtid = blockIdx.x * blockDim.x + threadIdx.x;
    int r = gtid >> 5;
    int lane = gtid & 31;
    if (r >= NN) return;
    int s = g_ptr1[r], e = g_ptr1[r + 1];
    float a0 = 0.f, a1 = 0.f;
    int i = s;
    for (; i + 1 < e; i += 2) {
        int2 ea = __ldg(&g_e1[i]);
        int2 eb = __ldg(&g_e1[i + 1]);
        uint32_t ta = __ldg(&g_sup1h[ea.x * 32 + lane]);
        uint32_t tb = __ldg(&g_sup1h[eb.x * 32 + lane]);
        float va = __int_as_float(ea.y), vb = __int_as_float(eb.y);
        float2 fa = __half22float2(*(__half2*)&ta);
        float2 fb = __half22float2(*(__half2*)&tb);
        a0 += va * fa.x + vb * fb.x;
        a1 += va * fa.y + vb * fb.y;
    }
    if (i < e) {
        int2 ea = __ldg(&g_e1[i]);
        float va = __int_as_float(ea.y);
        uint32_t ta = __ldg(&g_sup1h[ea.x * 32 + lane]);
        float2 fa = __half22float2(*(__half2*)&ta);
        a0 += va * fa.x; a1 += va * fa.y;
    }
    float2 b = ((const float2*)bias)[lane];
    out2[r * 32 + lane] = make_float2(a0 + b.x, a1 + b.y);
}

// ---------------- launch (single stream, 8 kernels) ------------------------
extern "C" void kernel_launch(void* const* d_in, const int* in_sizes, int n_in,
                              void* d_out, int out_size) {
    const float* x    = (const float*)d_in[0];
    const int*   row0 = (const int*)d_in[1];
    const int*   col0 = (const int*)d_in[2];
    const float* val0 = (const float*)d_in[3];
    const int*   row1 = (const int*)d_in[4];
    const int*   col1 = (const int*)d_in[5];
    const float* val1 = (const float*)d_in[6];
    const float* W0   = (const float*)d_in[7];
    const float* b0   = (const float*)d_in[8];
    const float* W1   = (const float*)d_in[9];
    const float* b1   = (const float*)d_in[10];
    float* out = (float*)d_out;

    const int TB = 256;
    const int SMEM_G0 = (128 * SA_H + 128 * (HIDF + 8)) * 2;  // 69632
    const int SMEM_G1 = (128 * SA_H + 128 * (OUTF + 8)) * 2;  // 53248
    cudaFuncSetAttribute(gemm0_mma, cudaFuncAttributeMaxDynamicSharedMemorySize, SMEM_G0);
    cudaFuncSetAttribute(gemm1_mma, cudaFuncAttributeMaxDynamicSharedMemorySize, SMEM_G1);

    // 1) support0 = fp16(x @ W0)
    gemm0_mma<<<(NN + 127) / 128, 256, SMEM_G0>>>(x, W0);

    // 2) histogram both layers (counters zero from previous run / static init)
    hist_kernel<<<(EE / 4 + TB - 1) / TB, TB>>>(row0, row1);

    // 3) scanA: local scans + last block scans block sums
    {
        dim3 g(NBLK, 2);
        scanA_kernel<<<g, SCAN_BLK>>>();
    }

    // 4) scanB: global offsets, cursors, re-zero counters
    {
        dim3 g(NBLK, 2);
        scanB_kernel<<<g, SCAN_BLK>>>();
    }

    // 5) counting-sort scatter (both layers, 8 edges/thread)
    {
        dim3 gs((EE / 8 + TB - 1) / TB, 2);
        scatter_kernel<<<gs, TB>>>(row0, col0, val0, row1, col1, val1);
    }

    // 6) h = fp16(relu(spmm(adj0, support0) + b0))
    spmm128_kernel<<<(NN * 32 + TB - 1) / TB, TB>>>(b0);

    // 7) support1 = fp16(h @ W1)
    gemm1_mma<<<(NN + 127) / 128, 256, SMEM_G1>>>(W1);

    // 8) out = spmm(adj1, support1) + b1
    spmm64_kernel<<<(NN * 32 + TB - 1) / TB, TB>>>(b1, (float2*)out);
}

// round 15
// speedup vs baseline: 1.3691x; 1.0104x over previous
#include <cuda_runtime.h>
#include <cuda_fp16.h>
#include <cstdint>

#define NN 50000
#define EE 800000
#define INF 128
#define HIDF 128
#define OUTF 64

#define SCAN_BLK 512
#define NBLK ((NN + SCAN_BLK - 1) / SCAN_BLK)   // 98

#define SA_H 136   // A smem row stride in halves (128 + 8 pad)

// ---------------- scratch (__device__ globals; no allocation allowed) ------
__device__ uint2    g_sup0h[NN * 32];   // fp16 support0 [NN][128]
__device__ uint2    g_hh[NN * 32];      // fp16 h        [NN][128]
__device__ uint32_t g_sup1h[NN * 32];   // fp16 support1 [NN][64]
__device__ int      g_cnt0[NN];         // zeroed inside scanA each run
__device__ int      g_cnt1[NN];
__device__ int      g_ptr0[NN + 1];     // TILE-LOCAL exclusive prefixes
__device__ int      g_ptr1[NN + 1];
__device__ int      g_cur0[NN];         // tile-local cursors
__device__ int      g_cur1[NN];
__device__ int      g_bsum[2][NBLK];
__device__ int      g_boff[2][NBLK];    // global tile offsets
__device__ int      g_done0, g_done1;   // scanA arrival counters (self-reset)
__device__ int2     g_e0[EE];           // (col, val-bits) sorted by row
__device__ int2     g_e1[EE];

// ---------------- helpers --------------------------------------------------
__device__ __forceinline__ uint32_t smem_u32(const void* p) {
    uint32_t a;
    asm("{ .reg .u64 t; cvta.to.shared.u64 t, %1; cvt.u32.u64 %0, t; }"
        : "=r"(a) : "l"(p));
    return a;
}
__device__ __forceinline__ void mma_f16(float& c0, float& c1, float& c2, float& c3,
                                        uint32_t a0, uint32_t a1, uint32_t a2, uint32_t a3,
                                        uint32_t b0, uint32_t b1) {
    asm volatile(
        "mma.sync.aligned.m16n8k16.row.col.f32.f16.f16.f32 "
        "{%0,%1,%2,%3}, {%4,%5,%6,%7}, {%8,%9}, {%0,%1,%2,%3};"
        : "+f"(c0), "+f"(c1), "+f"(c2), "+f"(c3)
        : "r"(a0), "r"(a1), "r"(a2), "r"(a3), "r"(b0), "r"(b1));
}
__device__ __forceinline__ void ldsm_x2_trans(uint32_t& r0, uint32_t& r1, uint32_t addr) {
    asm volatile("ldmatrix.sync.aligned.m8n8.x2.trans.shared.b16 {%0,%1}, [%2];"
                 : "=r"(r0), "=r"(r1) : "r"(addr));
}

// ---------------- histogram (both layers, int4) ----------------------------
__global__ void hist_kernel(const int* __restrict__ row0,
                            const int* __restrict__ row1) {
    int i = blockIdx.x * blockDim.x + threadIdx.x;
    if (i < EE / 4) {
        int4 r0 = ((const int4*)row0)[i];
        atomicAdd(&g_cnt0[r0.x], 1); atomicAdd(&g_cnt0[r0.y], 1);
        atomicAdd(&g_cnt0[r0.z], 1); atomicAdd(&g_cnt0[r0.w], 1);
        int4 r1 = ((const int4*)row1)[i];
        atomicAdd(&g_cnt1[r1.x], 1); atomicAdd(&g_cnt1[r1.y], 1);
        atomicAdd(&g_cnt1[r1.z], 1); atomicAdd(&g_cnt1[r1.w], 1);
    }
}

// ---------------- scanA: tile-local scan + cnt re-zero + tile-sum scan -----
// ptr/cur hold TILE-LOCAL prefixes; consumers add g_boff[tile] lazily.
__global__ void scanA_kernel() {
    __shared__ int s[SCAN_BLK];
    __shared__ int s_last;
    int which = blockIdx.y;
    int* __restrict__ cnt = which ? g_cnt1 : g_cnt0;
    int* __restrict__ ptr = which ? g_ptr1 : g_ptr0;
    int* __restrict__ cur = which ? g_cur1 : g_cur0;
    int tid = threadIdx.x;
    int i = blockIdx.x * SCAN_BLK + tid;
    int v = 0;
    if (i < NN) {
        v = cnt[i];
        cnt[i] = 0;                  // ready for next run's hist
    }
    s[tid] = v;
    __syncthreads();
#pragma unroll
    for (int off = 1; off < SCAN_BLK; off <<= 1) {
        int t = (tid >= off) ? s[tid - off] : 0;
        __syncthreads();
        s[tid] += t;
        __syncthreads();
    }
    int excl = s[tid] - v;
    if (i <= NN) ptr[i] = excl;      // i==NN gets tile-local total prefix
    if (i < NN) cur[i] = excl;
    if (tid == SCAN_BLK - 1) g_bsum[which][blockIdx.x] = s[tid];
    __threadfence();
    if (tid == 0) {
        int* done = which ? &g_done1 : &g_done0;
        int d = atomicAdd(done, 1);
        s_last = (d == NBLK - 1);
        if (s_last) *done = 0;
    }
    __syncthreads();
    if (!s_last) return;
    __threadfence();
    __shared__ int s2[128];
    int v2 = 0;
    if (tid < 128) {
        v2 = (tid < NBLK) ? g_bsum[which][tid] : 0;
        s2[tid] = v2;
    }
    __syncthreads();
#pragma unroll
    for (int off = 1; off < 128; off <<= 1) {
        int t = (tid >= off && tid < 128) ? s2[tid - off] : 0;
        __syncthreads();
        if (tid < 128) s2[tid] += t;
        __syncthreads();
    }
    if (tid < NBLK) g_boff[which][tid] = s2[tid] - v2;
}

// ---------------- counting-sort scatter (lazy global offsets) --------------
__global__ void scatter_kernel(const int* __restrict__ row0,
                               const int* __restrict__ col0,
                               const float* __restrict__ val0,
                               const int* __restrict__ row1,
                               const int* __restrict__ col1,
                               const float* __restrict__ val1) {
    int which = blockIdx.y;
    const int* __restrict__ row = which ? row1 : row0;
    const int* __restrict__ col = which ? col1 : col0;
    const int* __restrict__ val = (const int*)(which ? val1 : val0);
    int* __restrict__ cur = which ? g_cur1 : g_cur0;
    int2* __restrict__ ed = which ? g_e1 : g_e0;
    const int* __restrict__ boff = g_boff[which];
    int i = blockIdx.x * blockDim.x + threadIdx.x;
    if (i < EE / 4) {
        int4 r = ((const int4*)row)[i];
        int4 c = ((const int4*)col)[i];
        int4 v = ((const int4*)val)[i];
        int p;
        p = atomicAdd(&cur[r.x], 1) + boff[r.x >> 9]; ed[p] = make_int2(c.x, v.x);
        p = atomicAdd(&cur[r.y], 1) + boff[r.y >> 9]; ed[p] = make_int2(c.y, v.y);
        p = atomicAdd(&cur[r.z], 1) + boff[r.z >> 9]; ed[p] = make_int2(c.z, v.z);
        p = atomicAdd(&cur[r.w], 1) + boff[r.w >> 9]; ed[p] = make_int2(c.w, v.w);
    }
}

// ---------------- GEMM 0: support0h = fp16( x @ W0 ), f16 mma --------------
__global__ void __launch_bounds__(256, 2)
gemm0_mma(const float* __restrict__ x, const float* __restrict__ W0) {
    constexpr int NC = HIDF;         // 128
    constexpr int SBn = NC + 8;      // 136
    constexpr int WN = NC / 2, NT = WN / 8;   // 64, 8
    extern __shared__ __half smh[];
    __half* As = smh;                 // [128][SA_H]
    __half* Bs = smh + 128 * SA_H;    // [128][SBn]
    int tid = threadIdx.x, wid = tid >> 5, lane = tid & 31;
    int m0 = blockIdx.x * 128;
    int wm = (wid & 3) * 32, wn = (wid >> 2) * WN;
    int gr = lane >> 2, cq = lane & 3;

    const float4* A4 = (const float4*)x;
#pragma unroll
    for (int it = 0; it < 16; it++) {
        int idx = it * 256 + tid;
        int rr = idx >> 5, c4 = idx & 31;
        float4 v = make_float4(0.f, 0.f, 0.f, 0.f);
        int grow = m0 + rr;
        if (grow < NN) v = A4[grow * 32 + c4];
        __half2 h0 = __floats2half2_rn(v.x, v.y);
        __half2 h1 = __floats2half2_rn(v.z, v.w);
        uint2 pk;
        pk.x = *(uint32_t*)&h0; pk.y = *(uint32_t*)&h1;
        *(uint2*)&As[rr * SA_H + c4 * 4] = pk;
    }
    const float4* W4 = (const float4*)W0;
#pragma unroll
    for (int it = 0; it < (128 * NC / 4) / 256; it++) {
        int idx = it * 256 + tid;
        int kk = idx / (NC / 4), c4 = idx % (NC / 4);
        float4 v = W4[idx];
        __half2 h0 = __floats2half2_rn(v.x, v.y);
        __half2 h1 = __floats2half2_rn(v.z, v.w);
        uint2 pk;
        pk.x = *(uint32_t*)&h0; pk.y = *(uint32_t*)&h1;
        *(uint2*)&Bs[kk * SBn + c4 * 4] = pk;
    }
    __syncthreads();

    float acc[2][NT][4];
#pragma unroll
    for (int im = 0; im < 2; im++)
#pragma unroll
        for (int in = 0; in < NT; in++)
#pragma unroll
            for (int q = 0; q < 4; q++) acc[im][in][q] = 0.f;

#pragma unroll
    for (int ks = 0; ks < 8; ks++) {
        int k0 = ks * 16;
        uint32_t a[2][4];
#pragma unroll
        for (int im = 0; im < 2; im++) {
            int base = wm + im * 16;
            a[im][0] = *(uint32_t*)&As[(base + gr) * SA_H + k0 + 2 * cq];
            a[im][1] = *(uint32_t*)&As[(base + gr + 8) * SA_H + k0 + 2 * cq];
            a[im][2] = *(uint32_t*)&As[(base + gr) * SA_H + k0 + 2 * cq + 8];
            a[im][3] = *(uint32_t*)&As[(base + gr + 8) * SA_H + k0 + 2 * cq + 8];
        }
#pragma unroll
        for (int in = 0; in < NT; in++) {
            int n0 = wn + in * 8;
            uint32_t baddr = smem_u32(&Bs[(k0 + (lane & 15)) * SBn + n0]);
            uint32_t b0, b1;
            ldsm_x2_trans(b0, b1, baddr);
#pragma unroll
            for (int im = 0; im < 2; im++)
                mma_f16(acc[im][in][0], acc[im][in][1], acc[im][in][2], acc[im][in][3],
                        a[im][0], a[im][1], a[im][2], a[im][3], b0, b1);
        }
    }
    __half2* C2 = (__half2*)g_sup0h;     // [NN][64] half2
#pragma unroll
    for (int im = 0; im < 2; im++) {
        int row = m0 + wm + im * 16 + gr;
#pragma unroll
        for (int in = 0; in < NT; in++) {
            int colh = (wn + in * 8 + 2 * cq) >> 1;
            if (row < NN)
                C2[row * 64 + colh] = __floats2half2_rn(acc[im][in][0], acc[im][in][1]);
            if (row + 8 < NN)
                C2[(row + 8) * 64 + colh] = __floats2half2_rn(acc[im][in][2], acc[im][in][3]);
        }
    }
}

// ---------------- GEMM 1: support1h = fp16( h @ W1 ), f16 mma --------------
__global__ void __launch_bounds__(256, 2)
gemm1_mma(const float* __restrict__ W1) {
    constexpr int NC = OUTF;          // 64
    constexpr int SBn = NC + 8;       // 72
    constexpr int WN = NC / 2, NT = WN / 8;   // 32, 4
    extern __shared__ __half smh[];
    __half* As = smh;
    __half* Bs = smh + 128 * SA_H;
    int tid = threadIdx.x, wid = tid >> 5, lane = tid & 31;
    int m0 = blockIdx.x * 128;
    int wm = (wid & 3) * 32, wn = (wid >> 2) * WN;
    int gr = lane >> 2, cq = lane & 3;

#pragma unroll
    for (int it = 0; it < 16; it++) {
        int idx = it * 256 + tid;
        int rr = idx >> 5, c = idx & 31;
        uint2 t = make_uint2(0u, 0u);
        int grow = m0 + rr;
        if (grow < NN) t = g_hh[grow * 32 + c];
        *(uint2*)&As[rr * SA_H + c * 4] = t;
    }
    const float4* W4 = (const float4*)W1;
#pragma unroll
    for (int it = 0; it < (128 * NC / 4) / 256; it++) {
        int idx = it * 256 + tid;
        int kk = idx / (NC / 4), c4 = idx % (NC / 4);
        float4 v = W4[idx];
        __half2 h0 = __floats2half2_rn(v.x, v.y);
        __half2 h1 = __floats2half2_rn(v.z, v.w);
        uint2 pk;
        pk.x = *(uint32_t*)&h0; pk.y = *(uint32_t*)&h1;
        *(uint2*)&Bs[kk * SBn + c4 * 4] = pk;
    }
    __syncthreads();

    float acc[2][NT][4];
#pragma unroll
    for (int im = 0; im < 2; im++)
#pragma unroll
        for (int in = 0; in < NT; in++)
#pragma unroll
            for (int q = 0; q < 4; q++) acc[im][in][q] = 0.f;

#pragma unroll
    for (int ks = 0; ks < 8; ks++) {
        int k0 = ks * 16;
        uint32_t a[2][4];
#pragma unroll
        for (int im = 0; im < 2; im++) {
            int base = wm + im * 16;
            a[im][0] = *(uint32_t*)&As[(base + gr) * SA_H + k0 + 2 * cq];
            a[im][1] = *(uint32_t*)&As[(base + gr + 8) * SA_H + k0 + 2 * cq];
            a[im][2] = *(uint32_t*)&As[(base + gr) * SA_H + k0 + 2 * cq + 8];
            a[im][3] = *(uint32_t*)&As[(base + gr + 8) * SA_H + k0 + 2 * cq + 8];
        }
#pragma unroll
        for (int in = 0; in < NT; in++) {
            int n0 = wn + in * 8;
            uint32_t baddr = smem_u32(&Bs[(k0 + (lane & 15)) * SBn + n0]);
            uint32_t b0, b1;
            ldsm_x2_trans(b0, b1, baddr);
#pragma unroll
            for (int im = 0; im < 2; im++)
                mma_f16(acc[im][in][0], acc[im][in][1], acc[im][in][2], acc[im][in][3],
                        a[im][0], a[im][1], a[im][2], a[im][3], b0, b1);
        }
    }
    __half2* C2 = (__half2*)g_sup1h;     // [NN][32] half2
#pragma unroll
    for (int im = 0; im < 2; im++) {
        int row = m0 + wm + im * 16 + gr;
#pragma unroll
        for (int in = 0; in < NT; in++) {
            int colh = (wn + in * 8 + 2 * cq) >> 1;
            if (row < NN)
                C2[row * 32 + colh] = __floats2half2_rn(acc[im][in][0], acc[im][in][1]);
            if (row + 8 < NN)
                C2[(row + 8) * 32 + colh] = __floats2half2_rn(acc[im][in][2], acc[im][in][3]);
        }
    }
}

// ---------------- CSR row-gather SpMM, F=128 (lazy offsets) ----------------
__global__ void spmm128_kernel(const float* __restrict__ bias) {
    int gtid = blockIdx.x * blockDim.x + threadIdx.x;
    int r = gtid >> 5;
    int lane = gtid & 31;
    if (r >= NN) return;
    int s = g_ptr0[r] + g_boff[0][r >> 9];
    int e = g_ptr0[r + 1] + g_boff[0][(r + 1) >> 9];
    float a0 = 0.f, a1 = 0.f, a2 = 0.f, a3 = 0.f;
    int i = s;
    for (; i + 1 < e; i += 2) {
        int2 ea = __ldg(&g_e0[i]);
        int2 eb = __ldg(&g_e0[i + 1]);
        uint2 ta = __ldg(&g_sup0h[ea.x * 32 + lane]);
        uint2 tb = __ldg(&g_sup0h[eb.x * 32 + lane]);
        float va = __int_as_float(ea.y), vb = __int_as_float(eb.y);
        float2 fa0 = __half22float2(*(__half2*)&ta.x);
        float2 fa1 = __half22float2(*(__half2*)&ta.y);
        float2 fb0 = __half22float2(*(__half2*)&tb.x);
        float2 fb1 = __half22float2(*(__half2*)&tb.y);
        a0 += va * fa0.x + vb * fb0.x; a1 += va * fa0.y + vb * fb0.y;
        a2 += va * fa1.x + vb * fb1.x; a3 += va * fa1.y + vb * fb1.y;
    }
    if (i < e) {
        int2 ea = __ldg(&g_e0[i]);
        float va = __int_as_float(ea.y);
        uint2 ta = __ldg(&g_sup0h[ea.x * 32 + lane]);
        float2 fa0 = __half22float2(*(__half2*)&ta.x);
        float2 fa1 = __half22float2(*(__half2*)&ta.y);
        a0 += va * fa0.x; a1 += va * fa0.y; a2 += va * fa1.x; a3 += va * fa1.y;
    }
    float4 b = ((const float4*)bias)[lane];
    a0 = fmaxf(a0 + b.x, 0.f); a1 = fmaxf(a1 + b.y, 0.f);
    a2 = fmaxf(a2 + b.z, 0.f); a3 = fmaxf(a3 + b.w, 0.f);
    uint2 o;
    *(__half2*)&o.x = __floats2half2_rn(a0, a1);
    *(__half2*)&o.y = __floats2half2_rn(a2, a3);
    g_hh[r * 32 + lane] = o;
}

// ---------------- CSR row-gather SpMM, F=64 (lazy offsets) -----------------
__global__ void spmm64_kernel(const float* __restrict__ bias,
                              float2* __restrict__ out2) {
    int gtid = blockIdx.x * blockDim.x + threadIdx.x;
    int r = gtid >> 5;
    int lane = gtid & 31;
    if (r >= NN) return;
    int s = g_ptr1[r] + g_boff[1][r >> 9];
    int e = g_ptr1[r + 1] + g_boff[1][(r + 1) >> 9];
    float a0 = 0.f, a1 = 0.f;
    int i = s;
    for (; i + 1 < e; i += 2) {
        int2 ea = __ldg(&g_e1[i]);
        int2 eb = __ldg(&g_e1[i + 1]);
        uint32_t ta = __ldg(&g_sup1h[ea.x * 32 + lane]);
        uint32_t tb = __ldg(&g_sup1h[eb.x * 32 + lane]);
        float va = __int_as_float(ea.y), vb = __int_as_float(eb.y);
        float2 fa = __half22float2(*(__half2*)&ta);
        float2 fb = __half22float2(*(__half2*)&tb);
        a0 += va * fa.x + vb * fb.x;
        a1 += va * fa.y + vb * fb.y;
    }
    if (i < e) {
        int2 ea = __ldg(&g_e1[i]);
        float va = __int_as_float(ea.y);
        uint32_t ta = __ldg(&g_sup1h[ea.x * 32 + lane]);
        float2 fa = __half22float2(*(__half2*)&ta);
        a0 += va * fa.x; a1 += va * fa.y;
    }
    float2 b = ((const float2*)bias)[lane];
    out2[r * 32 + lane] = make_float2(a0 + b.x, a1 + b.y);
}

// ---------------- launch (single stream, 7 kernels) ------------------------
extern "C" void kernel_launch(void* const* d_in, const int* in_sizes, int n_in,
                              void* d_out, int out_size) {
    const float* x    = (const float*)d_in[0];
    const int*   row0 = (const int*)d_in[1];
    const int*   col0 = (const int*)d_in[2];
    const float* val0 = (const float*)d_in[3];
    const int*   row1 = (const int*)d_in[4];
    const int*   col1 = (const int*)d_in[5];
    const float* val1 = (const float*)d_in[6];
    const float* W0   = (const float*)d_in[7];
    const float* b0   = (const float*)d_in[8];
    const float* W1   = (const float*)d_in[9];
    const float* b1   = (const float*)d_in[10];
    float* out = (float*)d_out;

    const int TB = 256;
    const int SMEM_G0 = (128 * SA_H + 128 * (HIDF + 8)) * 2;  // 69632
    const int SMEM_G1 = (128 * SA_H + 128 * (OUTF + 8)) * 2;  // 53248
    cudaFuncSetAttribute(gemm0_mma, cudaFuncAttributeMaxDynamicSharedMemorySize, SMEM_G0);
    cudaFuncSetAttribute(gemm1_mma, cudaFuncAttributeMaxDynamicSharedMemorySize, SMEM_G1);

    // 1) support0 = fp16(x @ W0)
    gemm0_mma<<<(NN + 127) / 128, 256, SMEM_G0>>>(x, W0);

    // 2) histogram both layers
    hist_kernel<<<(EE / 4 + TB - 1) / TB, TB>>>(row0, row1);

    // 3) scanA: tile-local scans, cnt re-zero, tile-offset scan
    {
        dim3 g(NBLK, 2);
        scanA_kernel<<<g, SCAN_BLK>>>();
    }

    // 4) counting-sort scatter (lazy global offsets)
    {
        dim3 gs((EE / 4 + TB - 1) / TB, 2);
        scatter_kernel<<<gs, TB>>>(row0, col0, val0, row1, col1, val1);
    }

    // 5) h = fp16(relu(spmm(adj0, support0) + b0))
    spmm128_kernel<<<(NN * 32 + TB - 1) / TB, TB>>>(b0);

    // 6) support1 = fp16(h @ W1)
    gemm1_mma<<<(NN + 127) / 128, 256, SMEM_G1>>>(W1);

    // 7) out = spmm(adj1, support1) + b1
    spmm64_kernel<<<(NN * 32 + TB - 1) / TB, TB>>>(b1, (float2*)out);
}

// round 16
// speedup vs baseline: 1.4211x; 1.0380x over previous
#include <cuda_runtime.h>
#include <cuda_fp16.h>
#include <cstdint>

#define NN 50000
#define EE 800000
#define INF 128
#define HIDF 128
#define OUTF 64

#define SCAN_BLK 512
#define NBLK ((NN + SCAN_BLK - 1) / SCAN_BLK)   // 98

#define SA_H 136   // A smem row stride in halves (128 + 8 pad)

// ---------------- scratch (__device__ globals; no allocation allowed) ------
__device__ uint2    g_sup0h[NN * 32];   // fp16 support0 [NN][128]
__device__ uint2    g_hh[NN * 32];      // fp16 h        [NN][128]
__device__ uint32_t g_sup1h[NN * 32];   // fp16 support1 [NN][64]
__device__ int      g_cnt0[NN];         // zeroed inside scanA each run
__device__ int      g_cnt1[NN];
__device__ int      g_ptr0[NN + 1];     // TILE-LOCAL exclusive prefixes
__device__ int      g_ptr1[NN + 1];
__device__ int      g_bsum[2][NBLK];
__device__ int      g_boff[2][NBLK];    // global tile offsets
__device__ int      g_done0, g_done1;   // scanA arrival counters (self-reset)
__device__ ushort   g_rank0[EE];        // edge rank within its row (from hist)
__device__ ushort   g_rank1[EE];
__device__ int2     g_e0[EE];           // (col, val-bits) sorted by row
__device__ int2     g_e1[EE];

// ---------------- helpers --------------------------------------------------
__device__ __forceinline__ uint32_t smem_u32(const void* p) {
    uint32_t a;
    asm("{ .reg .u64 t; cvta.to.shared.u64 t, %1; cvt.u32.u64 %0, t; }"
        : "=r"(a) : "l"(p));
    return a;
}
__device__ __forceinline__ void mma_f16(float& c0, float& c1, float& c2, float& c3,
                                        uint32_t a0, uint32_t a1, uint32_t a2, uint32_t a3,
                                        uint32_t b0, uint32_t b1) {
    asm volatile(
        "mma.sync.aligned.m16n8k16.row.col.f32.f16.f16.f32 "
        "{%0,%1,%2,%3}, {%4,%5,%6,%7}, {%8,%9}, {%0,%1,%2,%3};"
        : "+f"(c0), "+f"(c1), "+f"(c2), "+f"(c3)
        : "r"(a0), "r"(a1), "r"(a2), "r"(a3), "r"(b0), "r"(b1));
}
__device__ __forceinline__ void ldsm_x2_trans(uint32_t& r0, uint32_t& r1, uint32_t addr) {
    asm volatile("ldmatrix.sync.aligned.m8n8.x2.trans.shared.b16 {%0,%1}, [%2];"
                 : "=r"(r0), "=r"(r1) : "r"(addr));
}

// ---------------- histogram + rank capture (both layers, int4) -------------
__global__ void hist_kernel(const int* __restrict__ row0,
                            const int* __restrict__ row1) {
    int i = blockIdx.x * blockDim.x + threadIdx.x;
    if (i < EE / 4) {
        int4 r0 = ((const int4*)row0)[i];
        ushort4 k0;
        k0.x = (ushort)atomicAdd(&g_cnt0[r0.x], 1);
        k0.y = (ushort)atomicAdd(&g_cnt0[r0.y], 1);
        k0.z = (ushort)atomicAdd(&g_cnt0[r0.z], 1);
        k0.w = (ushort)atomicAdd(&g_cnt0[r0.w], 1);
        ((ushort4*)g_rank0)[i] = k0;
        int4 r1 = ((const int4*)row1)[i];
        ushort4 k1;
        k1.x = (ushort)atomicAdd(&g_cnt1[r1.x], 1);
        k1.y = (ushort)atomicAdd(&g_cnt1[r1.y], 1);
        k1.z = (ushort)atomicAdd(&g_cnt1[r1.z], 1);
        k1.w = (ushort)atomicAdd(&g_cnt1[r1.w], 1);
        ((ushort4*)g_rank1)[i] = k1;
    }
}

// ---------------- scanA: tile-local scan + cnt re-zero + tile-sum scan -----
// ptr holds TILE-LOCAL prefixes; consumers add g_boff[tile] lazily.
__global__ void scanA_kernel() {
    __shared__ int s[SCAN_BLK];
    __shared__ int s_last;
    int which = blockIdx.y;
    int* __restrict__ cnt = which ? g_cnt1 : g_cnt0;
    int* __restrict__ ptr = which ? g_ptr1 : g_ptr0;
    int tid = threadIdx.x;
    int i = blockIdx.x * SCAN_BLK + tid;
    int v = 0;
    if (i < NN) {
        v = cnt[i];
        cnt[i] = 0;                  // ready for next run's hist
    }
    s[tid] = v;
    __syncthreads();
#pragma unroll
    for (int off = 1; off < SCAN_BLK; off <<= 1) {
        int t = (tid >= off) ? s[tid - off] : 0;
        __syncthreads();
        s[tid] += t;
        __syncthreads();
    }
    int excl = s[tid] - v;
    if (i <= NN) ptr[i] = excl;      // i==NN gets tile-local total prefix
    if (tid == SCAN_BLK - 1) g_bsum[which][blockIdx.x] = s[tid];
    __threadfence();
    if (tid == 0) {
        int* done = which ? &g_done1 : &g_done0;
        int d = atomicAdd(done, 1);
        s_last = (d == NBLK - 1);
        if (s_last) *done = 0;
    }
    __syncthreads();
    if (!s_last) return;
    __threadfence();
    __shared__ int s2[128];
    int v2 = 0;
    if (tid < 128) {
        v2 = (tid < NBLK) ? g_bsum[which][tid] : 0;
        s2[tid] = v2;
    }
    __syncthreads();
#pragma unroll
    for (int off = 1; off < 128; off <<= 1) {
        int t = (tid >= off && tid < 128) ? s2[tid - off] : 0;
        __syncthreads();
        if (tid < 128) s2[tid] += t;
        __syncthreads();
    }
    if (tid < NBLK) g_boff[which][tid] = s2[tid] - v2;
}

// ---------------- scatter: atomic-free (rank from hist) --------------------
__global__ void scatter_kernel(const int* __restrict__ row0,
                               const int* __restrict__ col0,
                               const float* __restrict__ val0,
                               const int* __restrict__ row1,
                               const int* __restrict__ col1,
                               const float* __restrict__ val1) {
    int which = blockIdx.y;
    const int* __restrict__ row = which ? row1 : row0;
    const int* __restrict__ col = which ? col1 : col0;
    const int* __restrict__ val = (const int*)(which ? val1 : val0);
    const int* __restrict__ ptr = which ? g_ptr1 : g_ptr0;
    const ushort* __restrict__ rank = which ? g_rank1 : g_rank0;
    int2* __restrict__ ed = which ? g_e1 : g_e0;
    const int* __restrict__ boff = g_boff[which];
    int i = blockIdx.x * blockDim.x + threadIdx.x;
    if (i < EE / 4) {
        int4 r = ((const int4*)row)[i];
        int4 c = ((const int4*)col)[i];
        int4 v = ((const int4*)val)[i];
        ushort4 k = ((const ushort4*)rank)[i];
        int p;
        p = ptr[r.x] + boff[r.x >> 9] + k.x; ed[p] = make_int2(c.x, v.x);
        p = ptr[r.y] + boff[r.y >> 9] + k.y; ed[p] = make_int2(c.y, v.y);
        p = ptr[r.z] + boff[r.z >> 9] + k.z; ed[p] = make_int2(c.z, v.z);
        p = ptr[r.w] + boff[r.w >> 9] + k.w; ed[p] = make_int2(c.w, v.w);
    }
}

// ---------------- GEMM 0: support0h = fp16( x @ W0 ), f16 mma --------------
__global__ void __launch_bounds__(256, 2)
gemm0_mma(const float* __restrict__ x, const float* __restrict__ W0) {
    constexpr int NC = HIDF;         // 128
    constexpr int SBn = NC + 8;      // 136
    constexpr int WN = NC / 2, NT = WN / 8;   // 64, 8
    extern __shared__ __half smh[];
    __half* As = smh;                 // [128][SA_H]
    __half* Bs = smh + 128 * SA_H;    // [128][SBn]
    int tid = threadIdx.x, wid = tid >> 5, lane = tid & 31;
    int m0 = blockIdx.x * 128;
    int wm = (wid & 3) * 32, wn = (wid >> 2) * WN;
    int gr = lane >> 2, cq = lane & 3;

    const float4* A4 = (const float4*)x;
#pragma unroll
    for (int it = 0; it < 16; it++) {
        int idx = it * 256 + tid;
        int rr = idx >> 5, c4 = idx & 31;
        float4 v = make_float4(0.f, 0.f, 0.f, 0.f);
        int grow = m0 + rr;
        if (grow < NN) v = A4[grow * 32 + c4];
        __half2 h0 = __floats2half2_rn(v.x, v.y);
        __half2 h1 = __floats2half2_rn(v.z, v.w);
        uint2 pk;
        pk.x = *(uint32_t*)&h0; pk.y = *(uint32_t*)&h1;
        *(uint2*)&As[rr * SA_H + c4 * 4] = pk;
    }
    const float4* W4 = (const float4*)W0;
#pragma unroll
    for (int it = 0; it < (128 * NC / 4) / 256; it++) {
        int idx = it * 256 + tid;
        int kk = idx / (NC / 4), c4 = idx % (NC / 4);
        float4 v = W4[idx];
        __half2 h0 = __floats2half2_rn(v.x, v.y);
        __half2 h1 = __floats2half2_rn(v.z, v.w);
        uint2 pk;
        pk.x = *(uint32_t*)&h0; pk.y = *(uint32_t*)&h1;
        *(uint2*)&Bs[kk * SBn + c4 * 4] = pk;
    }
    __syncthreads();

    float acc[2][NT][4];
#pragma unroll
    for (int im = 0; im < 2; im++)
#pragma unroll
        for (int in = 0; in < NT; in++)
#pragma unroll
            for (int q = 0; q < 4; q++) acc[im][in][q] = 0.f;

#pragma unroll
    for (int ks = 0; ks < 8; ks++) {
        int k0 = ks * 16;
        uint32_t a[2][4];
#pragma unroll
        for (int im = 0; im < 2; im++) {
            int base = wm + im * 16;
            a[im][0] = *(uint32_t*)&As[(base + gr) * SA_H + k0 + 2 * cq];
            a[im][1] = *(uint32_t*)&As[(base + gr + 8) * SA_H + k0 + 2 * cq];
            a[im][2] = *(uint32_t*)&As[(base + gr) * SA_H + k0 + 2 * cq + 8];
            a[im][3] = *(uint32_t*)&As[(base + gr + 8) * SA_H + k0 + 2 * cq + 8];
        }
#pragma unroll
        for (int in = 0; in < NT; in++) {
            int n0 = wn + in * 8;
            uint32_t baddr = smem_u32(&Bs[(k0 + (lane & 15)) * SBn + n0]);
            uint32_t b0, b1;
            ldsm_x2_trans(b0, b1, baddr);
#pragma unroll
            for (int im = 0; im < 2; im++)
                mma_f16(acc[im][in][0], acc[im][in][1], acc[im][in][2], acc[im][in][3],
                        a[im][0], a[im][1], a[im][2], a[im][3], b0, b1);
        }
    }
    __half2* C2 = (__half2*)g_sup0h;     // [NN][64] half2
#pragma unroll
    for (int im = 0; im < 2; im++) {
        int row = m0 + wm + im * 16 + gr;
#pragma unroll
        for (int in = 0; in < NT; in++) {
            int colh = (wn + in * 8 + 2 * cq) >> 1;
            if (row < NN)
                C2[row * 64 + colh] = __floats2half2_rn(acc[im][in][0], acc[im][in][1]);
            if (row + 8 < NN)
                C2[(row + 8) * 64 + colh] = __floats2half2_rn(acc[im][in][2], acc[im][in][3]);
        }
    }
}

// ---------------- GEMM 1: support1h = fp16( h @ W1 ), f16 mma --------------
__global__ void __launch_bounds__(256, 2)
gemm1_mma(const float* __restrict__ W1) {
    constexpr int NC = OUTF;          // 64
    constexpr int SBn = NC + 8;       // 72
    constexpr int WN = NC / 2, NT = WN / 8;   // 32, 4
    extern __shared__ __half smh[];
    __half* As = smh;
    __half* Bs = smh + 128 * SA_H;
    int tid = threadIdx.x, wid = tid >> 5, lane = tid & 31;
    int m0 = blockIdx.x * 128;
    int wm = (wid & 3) * 32, wn = (wid >> 2) * WN;
    int gr = lane >> 2, cq = lane & 3;

#pragma unroll
    for (int it = 0; it < 16; it++) {
        int idx = it * 256 + tid;
        int rr = idx >> 5, c = idx & 31;
        uint2 t = make_uint2(0u, 0u);
        int grow = m0 + rr;
        if (grow < NN) t = g_hh[grow * 32 + c];
        *(uint2*)&As[rr * SA_H + c * 4] = t;
    }
    const float4* W4 = (const float4*)W1;
#pragma unroll
    for (int it = 0; it < (128 * NC / 4) / 256; it++) {
        int idx = it * 256 + tid;
        int kk = idx / (NC / 4), c4 = idx % (NC / 4);
        float4 v = W4[idx];
        __half2 h0 = __floats2half2_rn(v.x, v.y);
        __half2 h1 = __floats2half2_rn(v.z, v.w);
        uint2 pk;
        pk.x = *(uint32_t*)&h0; pk.y = *(uint32_t*)&h1;
        *(uint2*)&Bs[kk * SBn + c4 * 4] = pk;
    }
    __syncthreads();

    float acc[2][NT][4];
#pragma unroll
    for (int im = 0; im < 2; im++)
#pragma unroll
        for (int in = 0; in < NT; in++)
#pragma unroll
            for (int q = 0; q < 4; q++) acc[im][in][q] = 0.f;

#pragma unroll
    for (int ks = 0; ks < 8; ks++) {
        int k0 = ks * 16;
        uint32_t a[2][4];
#pragma unroll
        for (int im = 0; im < 2; im++) {
            int base = wm + im * 16;
            a[im][0] = *(uint32_t*)&As[(base + gr) * SA_H + k0 + 2 * cq];
            a[im][1] = *(uint32_t*)&As[(base + gr + 8) * SA_H + k0 + 2 * cq];
            a[im][2] = *(uint32_t*)&As[(base + gr) * SA_H + k0 + 2 * cq + 8];
            a[im][3] = *(uint32_t*)&As[(base + gr + 8) * SA_H + k0 + 2 * cq + 8];
        }
#pragma unroll
        for (int in = 0; in < NT; in++) {
            int n0 = wn + in * 8;
            uint32_t baddr = smem_u32(&Bs[(k0 + (lane & 15)) * SBn + n0]);
            uint32_t b0, b1;
            ldsm_x2_trans(b0, b1, baddr);
#pragma unroll
            for (int im = 0; im < 2; im++)
                mma_f16(acc[im][in][0], acc[im][in][1], acc[im][in][2], acc[im][in][3],
                        a[im][0], a[im][1], a[im][2], a[im][3], b0, b1);
        }
    }
    __half2* C2 = (__half2*)g_sup1h;     // [NN][32] half2
#pragma unroll
    for (int im = 0; im < 2; im++) {
        int row = m0 + wm + im * 16 + gr;
#pragma unroll
        for (int in = 0; in < NT; in++) {
            int colh = (wn + in * 8 + 2 * cq) >> 1;
            if (row < NN)
                C2[row * 32 + colh] = __floats2half2_rn(acc[im][in][0], acc[im][in][1]);
            if (row + 8 < NN)
                C2[(row + 8) * 32 + colh] = __floats2half2_rn(acc[im][in][2], acc[im][in][3]);
        }
    }
}

// ---------------- CSR row-gather SpMM, F=128 (lazy offsets) ----------------
__global__ void spmm128_kernel(const float* __restrict__ bias) {
    int gtid = blockIdx.x * blockDim.x + threadIdx.x;
    int r = gtid >> 5;
    int lane = gtid & 31;
    if (r >= NN) return;
    int s = g_ptr0[r] + g_boff[0][r >> 9];
    int e = g_ptr0[r + 1] + g_boff[0][(r + 1) >> 9];
    float a0 = 0.f, a1 = 0.f, a2 = 0.f, a3 = 0.f;
    int i = s;
    for (; i + 1 < e; i += 2) {
        int2 ea = __ldg(&g_e0[i]);
        int2 eb = __ldg(&g_e0[i + 1]);
        uint2 ta = __ldg(&g_sup0h[ea.x * 32 + lane]);
        uint2 tb = __ldg(&g_sup0h[eb.x * 32 + lane]);
        float va = __int_as_float(ea.y), vb = __int_as_float(eb.y);
        float2 fa0 = __half22float2(*(__half2*)&ta.x);
        float2 fa1 = __half22float2(*(__half2*)&ta.y);
        float2 fb0 = __half22float2(*(__half2*)&tb.x);
        float2 fb1 = __half22float2(*(__half2*)&tb.y);
        a0 += va * fa0.x + vb * fb0.x; a1 += va * fa0.y + vb * fb0.y;
        a2 += va * fa1.x + vb * fb1.x; a3 += va * fa1.y + vb * fb1.y;
    }
    if (i < e) {
        int2 ea = __ldg(&g_e0[i]);
        float va = __int_as_float(ea.y);
        uint2 ta = __ldg(&g_sup0h[ea.x * 32 + lane]);
        float2 fa0 = __half22float2(*(__half2*)&ta.x);
        float2 fa1 = __half22float2(*(__half2*)&ta.y);
        a0 += va * fa0.x; a1 += va * fa0.y; a2 += va * fa1.x; a3 += va * fa1.y;
    }
    float4 b = ((const float4*)bias)[lane];
    a0 = fmaxf(a0 + b.x, 0.f); a1 = fmaxf(a1 + b.y, 0.f);
    a2 = fmaxf(a2 + b.z, 0.f); a3 = fmaxf(a3 + b.w, 0.f);
    uint2 o;
    *(__half2*)&o.x = __floats2half2_rn(a0, a1);
    *(__half2*)&o.y = __floats2half2_rn(a2, a3);
    g_hh[r * 32 + lane] = o;
}

// ---------------- CSR row-gather SpMM, F=64 (lazy offsets) -----------------
__global__ void spmm64_kernel(const float* __restrict__ bias,
                              float2* __restrict__ out2) {
    int gtid = blockIdx.x * blockDim.x + threadIdx.x;
    int r = gtid >> 5;
    int lane = gtid & 31;
    if (r >= NN) return;
    int s = g_ptr1[r] + g_boff[1][r >> 9];
    int e = g_ptr1[r + 1] + g_boff[1][(r + 1) >> 9];
    float a0 = 0.f, a1 = 0.f;
    int i = s;
    for (; i + 1 < e; i += 2) {
        int2 ea = __ldg(&g_e1[i]);
        int2 eb = __ldg(&g_e1[i + 1]);
        uint32_t ta = __ldg(&g_sup1h[ea.x * 32 + lane]);
        uint32_t tb = __ldg(&g_sup1h[eb.x * 32 + lane]);
        float va = __int_as_float(ea.y), vb = __int_as_float(eb.y);
        float2 fa = __half22float2(*(__half2*)&ta);
        float2 fb = __half22float2(*(__half2*)&tb);
        a0 += va * fa.x + vb * fb.x;
        a1 += va * fa.y + vb * fb.y;
    }
    if (i < e) {
        int2 ea = __ldg(&g_e1[i]);
        float va = __int_as_float(ea.y);
        uint32_t ta = __ldg(&g_sup1h[ea.x * 32 + lane]);
        float2 fa = __half22float2(*(__half2*)&ta);
        a0 += va * fa.x; a1 += va * fa.y;
    }
    float2 b = ((const float2*)bias)[lane];
    out2[r * 32 + lane] = make_float2(a0 + b.x, a1 + b.y);
}

// ---------------- launch (single stream, 7 kernels) ------------------------
extern "C" void kernel_launch(void* const* d_in, const int* in_sizes, int n_in,
                              void* d_out, int out_size) {
    const float* x    = (const float*)d_in[0];
    const int*   row0 = (const int*)d_in[1];
    const int*   col0 = (const int*)d_in[2];
    const float* val0 = (const float*)d_in[3];
    const int*   row1 = (const int*)d_in[4];
    const int*   col1 = (const int*)d_in[5];
    const float* val1 = (const float*)d_in[6];
    const float* W0   = (const float*)d_in[7];
    const float* b0   = (const float*)d_in[8];
    const float* W1   = (const float*)d_in[9];
    const float* b1   = (const float*)d_in[10];
    float* out = (float*)d_out;

    const int TB = 256;
    const int SMEM_G0 = (128 * SA_H + 128 * (HIDF + 8)) * 2;  // 69632
    const int SMEM_G1 = (128 * SA_H + 128 * (OUTF + 8)) * 2;  // 53248
    cudaFuncSetAttribute(gemm0_mma, cudaFuncAttributeMaxDynamicSharedMemorySize, SMEM_G0);
    cudaFuncSetAttribute(gemm1_mma, cudaFuncAttributeMaxDynamicSharedMemorySize, SMEM_G1);

    // 1) support0 = fp16(x @ W0)
    gemm0_mma<<<(NN + 127) / 128, 256, SMEM_G0>>>(x, W0);

    // 2) histogram both layers + per-edge rank capture
    hist_kernel<<<(EE / 4 + TB - 1) / TB, TB>>>(row0, row1);

    // 3) scanA: tile-local scans, cnt re-zero, tile-offset scan
    {
        dim3 g(NBLK, 2);
        scanA_kernel<<<g, SCAN_BLK>>>();
    }

    // 4) scatter: atomic-free placement via hist ranks
    {
        dim3 gs((EE / 4 + TB - 1) / TB, 2);
        scatter_kernel<<<gs, TB>>>(row0, col0, val0, row1, col1, val1);
    }

    // 5) h = fp16(relu(spmm(adj0, support0) + b0))
    spmm128_kernel<<<(NN * 32 + TB - 1) / TB, TB>>>(b0);

    // 6) support1 = fp16(h @ W1)
    gemm1_mma<<<(NN + 127) / 128, 256, SMEM_G1>>>(W1);

    // 7) out = spmm(adj1, support1) + b1
    spmm64_kernel<<<(NN * 32 + TB - 1) / TB, TB>>>(b1, (float2*)out);
}